// round 2
// baseline (speedup 1.0000x reference)
#include <cuda_runtime.h>

// Bundle-adjustment reprojection residual.
// Inputs (metadata order):
//   d_in[0] observes  float32 [N_OBS, 2]
//   d_in[1] K         float32 [3, 3]
//   d_in[2] poses     float32 [N_CAM, 7]   (t[3], qv[3], qw)
//   d_in[3] points    float32 [N_PTS, 3]
//   d_in[4] cidx      int32   [N_OBS]   (JAX x64 disabled -> int32)
//   d_in[5] pidx      int32   [N_OBS]
// Output: float32 [N_OBS*2]  residual = proj - observe

__global__ __launch_bounds__(256) void residual_kernel(
    const float2* __restrict__ observes,
    const float* __restrict__ K,
    const float* __restrict__ poses,
    const float* __restrict__ points,
    const int* __restrict__ cidx,
    const int* __restrict__ pidx,
    float2* __restrict__ out,
    int n_obs)
{
    int i = blockIdx.x * blockDim.x + threadIdx.x;
    if (i >= n_obs) return;

    // K is row-major 3x3: [fx 0 cx; 0 fy cy; 0 0 1]
    // img = p_cam @ K^T -> img0 = fx*x + cx*z ; img1 = fy*y + cy*z ; img2 = z
    const float fx = __ldg(&K[0]);
    const float cx = __ldg(&K[2]);
    const float fy = __ldg(&K[4]);
    const float cy = __ldg(&K[5]);

    const int ci = __ldg(&cidx[i]);
    const int pi = __ldg(&pidx[i]);

    const float* po = poses + (size_t)ci * 7;
    float tx = __ldg(po + 0);
    float ty = __ldg(po + 1);
    float tz = __ldg(po + 2);
    float qx = __ldg(po + 3);
    float qy = __ldg(po + 4);
    float qz = __ldg(po + 5);
    float qw = __ldg(po + 6);

    const float* pt = points + (size_t)pi * 3;
    float px = __ldg(pt + 0);
    float py = __ldg(pt + 1);
    float pz = __ldg(pt + 2);

    // uv = cross(qv, p)
    float uvx = qy * pz - qz * py;
    float uvy = qz * px - qx * pz;
    float uvz = qx * py - qy * px;

    // w = uv + qw * p
    float wx = fmaf(qw, px, uvx);
    float wy = fmaf(qw, py, uvy);
    float wz = fmaf(qw, pz, uvz);

    // cross(qv, w)
    float cx2 = qy * wz - qz * wy;
    float cy2 = qz * wx - qx * wz;
    float cz2 = qx * wy - qy * wx;

    // p_cam = p + 2*cross(qv, w) + t
    float Xc = fmaf(2.0f, cx2, px) + tx;
    float Yc = fmaf(2.0f, cy2, py) + ty;
    float Zc = fmaf(2.0f, cz2, pz) + tz;

    float invz = __fdividef(1.0f, Zc);

    float2 obs = __ldg(&observes[i]);
    float2 r;
    r.x = fmaf(fx * Xc, invz, cx) - obs.x;
    r.y = fmaf(fy * Yc, invz, cy) - obs.y;
    out[i] = r;
}

extern "C" void kernel_launch(void* const* d_in, const int* in_sizes, int n_in,
                              void* d_out, int out_size) {
    const float2* observes = (const float2*)d_in[0];
    const float* K          = (const float*)d_in[1];
    const float* poses      = (const float*)d_in[2];
    const float* points     = (const float*)d_in[3];
    const int* cidx         = (const int*)d_in[4];
    const int* pidx         = (const int*)d_in[5];
    float2* out             = (float2*)d_out;

    int n_obs = in_sizes[0] / 2;  // observes has N_OBS*2 elements
    int threads = 256;
    int blocks = (n_obs + threads - 1) / threads;
    residual_kernel<<<blocks, threads>>>(observes, K, poses, points, cidx, pidx, out, n_obs);
}

// round 4
// speedup vs baseline: 1.8096x; 1.8096x over previous
#include <cuda_runtime.h>

// Bundle-adjustment reprojection residual.
// Inputs (metadata order):
//   d_in[0] observes  float32 [N_OBS, 2]
//   d_in[1] K         float32 [3, 3]
//   d_in[2] poses     float32 [N_CAM, 7]   (t[3], qv[3], qw)
//   d_in[3] points    float32 [N_PTS, 3]
//   d_in[4] cidx      int32   [N_OBS]
//   d_in[5] pidx      int32   [N_OBS]
// Output: float32 [N_OBS*2]  residual = proj - observe
//
// Strategy: pose table (2000x7 = 56KB) staged in shared memory padded to
// 8 floats/cam (62.5KB), gathered with 2x LDS.128. Streams (idx/obs/out)
// vectorized 4 obs per thread. Point gather stays in L1/L2 (6MB table).

#define THREADS 256
#define N_CAM_MAX 2000   // known from problem; smem sized for it

__global__ __launch_bounds__(THREADS, 3) void residual_kernel(
    const float4* __restrict__ obs4,      // observes as float4 (2 obs each)
    const float* __restrict__ K,
    const float* __restrict__ poses,
    const float* __restrict__ points,
    const int4* __restrict__ cidx4,
    const int4* __restrict__ pidx4,
    const int* __restrict__ cidx,         // scalar views for tail
    const int* __restrict__ pidx,
    const float2* __restrict__ obs2,
    float4* __restrict__ out4,
    float2* __restrict__ out2,
    int n_obs, int n_cam)
{
    extern __shared__ float psm[];  // [n_cam * 8]

    const int tid = threadIdx.x;

    // Stage poses: 7 floats/cam -> 8-float padded rows in smem.
    const int n_pose_f = n_cam * 7;
    for (int idx = tid; idx < n_pose_f; idx += THREADS) {
        int c = idx / 7;
        int k = idx - c * 7;
        psm[c * 8 + k] = __ldg(&poses[idx]);
    }
    __syncthreads();

    const float fx = __ldg(&K[0]);
    const float cxx = __ldg(&K[2]);
    const float fy = __ldg(&K[4]);
    const float cyy = __ldg(&K[5]);

    const int n_quads = n_obs >> 2;
    const int gsz = gridDim.x * THREADS;

    for (int q = blockIdx.x * THREADS + tid; q < n_quads; q += gsz) {
        // ---- issue all independent loads up front (MLP) ----
        int4 c4 = __ldg(&cidx4[q]);
        int4 p4 = __ldg(&pidx4[q]);

        float4 ob0 = __ldg(&obs4[2 * q]);
        float4 ob1 = __ldg(&obs4[2 * q + 1]);

        int pis[4] = {p4.x, p4.y, p4.z, p4.w};
        int cis[4] = {c4.x, c4.y, c4.z, c4.w};

        float px[4], py[4], pz[4];
        #pragma unroll
        for (int j = 0; j < 4; j++) {
            const float* pt = points + (size_t)pis[j] * 3;
            px[j] = __ldg(pt + 0);
            py[j] = __ldg(pt + 1);
            pz[j] = __ldg(pt + 2);
        }

        float4 pa[4], pb[4];
        #pragma unroll
        for (int j = 0; j < 4; j++) {
            const float4* row = (const float4*)(psm + cis[j] * 8);
            pa[j] = row[0];   // tx ty tz qx
            pb[j] = row[1];   // qy qz qw --
        }

        float res[8];
        float obx[4] = {ob0.x, ob0.z, ob1.x, ob1.z};
        float oby[4] = {ob0.y, ob0.w, ob1.y, ob1.w};

        #pragma unroll
        for (int j = 0; j < 4; j++) {
            float tx = pa[j].x, ty = pa[j].y, tz = pa[j].z;
            float qx = pa[j].w, qy = pb[j].x, qz = pb[j].y, qw = pb[j].z;
            float X = px[j], Y = py[j], Z = pz[j];

            // uv = cross(qv, p)
            float uvx = qy * Z - qz * Y;
            float uvy = qz * X - qx * Z;
            float uvz = qx * Y - qy * X;
            // w = uv + qw*p
            float wx = fmaf(qw, X, uvx);
            float wy = fmaf(qw, Y, uvy);
            float wz = fmaf(qw, Z, uvz);
            // cross(qv, w)
            float c2x = qy * wz - qz * wy;
            float c2y = qz * wx - qx * wz;
            float c2z = qx * wy - qy * wx;
            // p_cam
            float Xc = fmaf(2.0f, c2x, X) + tx;
            float Yc = fmaf(2.0f, c2y, Y) + ty;
            float Zc = fmaf(2.0f, c2z, Z) + tz;

            float invz = __fdividef(1.0f, Zc);
            res[2 * j + 0] = fmaf(fx * Xc, invz, cxx) - obx[j];
            res[2 * j + 1] = fmaf(fy * Yc, invz, cyy) - oby[j];
        }

        out4[2 * q]     = make_float4(res[0], res[1], res[2], res[3]);
        out4[2 * q + 1] = make_float4(res[4], res[5], res[6], res[7]);
    }

    // ---- tail: n_obs % 4 leftover observations (block 0 only) ----
    const int rem_base = n_quads << 2;
    if (blockIdx.x == 0) {
        for (int i = rem_base + tid; i < n_obs; i += THREADS) {
            int ci = __ldg(&cidx[i]);
            int pi = __ldg(&pidx[i]);
            const float* row = psm + ci * 8;
            float tx = row[0], ty = row[1], tz = row[2];
            float qx = row[3], qy = row[4], qz = row[5], qw = row[6];
            const float* pt = points + (size_t)pi * 3;
            float X = __ldg(pt + 0), Y = __ldg(pt + 1), Z = __ldg(pt + 2);

            float uvx = qy * Z - qz * Y;
            float uvy = qz * X - qx * Z;
            float uvz = qx * Y - qy * X;
            float wx = fmaf(qw, X, uvx);
            float wy = fmaf(qw, Y, uvy);
            float wz = fmaf(qw, Z, uvz);
            float c2x = qy * wz - qz * wy;
            float c2y = qz * wx - qx * wz;
            float c2z = qx * wy - qy * wx;
            float Xc = fmaf(2.0f, c2x, X) + tx;
            float Yc = fmaf(2.0f, c2y, Y) + ty;
            float Zc = fmaf(2.0f, c2z, Z) + tz;
            float invz = __fdividef(1.0f, Zc);
            float2 ob = __ldg(&obs2[i]);
            float2 r;
            r.x = fmaf(fx * Xc, invz, cxx) - ob.x;
            r.y = fmaf(fy * Yc, invz, cyy) - ob.y;
            out2[i] = r;
        }
    }
}

extern "C" void kernel_launch(void* const* d_in, const int* in_sizes, int n_in,
                              void* d_out, int out_size) {
    const float* observes = (const float*)d_in[0];
    const float* K        = (const float*)d_in[1];
    const float* poses    = (const float*)d_in[2];
    const float* points   = (const float*)d_in[3];
    const int* cidx       = (const int*)d_in[4];
    const int* pidx       = (const int*)d_in[5];

    int n_obs = in_sizes[0] / 2;
    int n_cam = in_sizes[2] / 7;

    int smem = n_cam * 8 * sizeof(float);  // 64000 B for n_cam=2000

    static bool attr_set = false;
    if (!attr_set) {
        cudaFuncSetAttribute(residual_kernel,
                             cudaFuncAttributeMaxDynamicSharedMemorySize, smem);
        attr_set = true;
    }

    int blocks = 148 * 3;  // persistent-ish, 3 blocks/SM (smem-limited)

    residual_kernel<<<blocks, THREADS, smem>>>(
        (const float4*)observes, K, poses, points,
        (const int4*)cidx, (const int4*)pidx,
        cidx, pidx, (const float2*)observes,
        (float4*)d_out, (float2*)d_out,
        n_obs, n_cam);
}

// round 7
// speedup vs baseline: 2.3127x; 1.2780x over previous
#include <cuda_runtime.h>

// Bundle-adjustment reprojection residual.
//   d_in[0] observes  float32 [N_OBS, 2]
//   d_in[1] K         float32 [3, 3]
//   d_in[2] poses     float32 [N_CAM, 7]   (t[3], qv[3], qw)
//   d_in[3] points    float32 [N_PTS, 3]
//   d_in[4] cidx      int32   [N_OBS]
//   d_in[5] pidx      int32   [N_OBS]
// Output: float32 [N_OBS*2]  residual = proj - observe
//
// Strategy:
//  - prologue kernel repacks points into float4 (one LDG.128 per gather)
//  - pose table staged in smem with 12-float stride (conflict-free LDS.128)
//  - 512-thread blocks, 2/SM, 4 obs per thread, fully vectorized streams

#define THREADS 512
#define N_PTS_MAX 500032
#define POSE_STRIDE 12   // floats per pose row in smem (48B: spreads bank starts)

__device__ float4 g_points4[N_PTS_MAX];

__global__ __launch_bounds__(256) void repack_points_kernel(
    const float* __restrict__ points, int n_pts)
{
    int i = blockIdx.x * blockDim.x + threadIdx.x;
    if (i >= n_pts) return;
    const float* p = points + (size_t)i * 3;
    g_points4[i] = make_float4(__ldg(p), __ldg(p + 1), __ldg(p + 2), 0.0f);
}

__global__ __launch_bounds__(THREADS, 2) void residual_kernel(
    const float4* __restrict__ obs4,
    const float* __restrict__ K,
    const float* __restrict__ poses,
    const int4* __restrict__ cidx4,
    const int4* __restrict__ pidx4,
    const int* __restrict__ cidx,
    const int* __restrict__ pidx,
    const float2* __restrict__ obs2,
    float4* __restrict__ out4,
    float2* __restrict__ out2,
    int n_obs, int n_cam)
{
    extern __shared__ float psm[];  // [n_cam * POSE_STRIDE]

    const int tid = threadIdx.x;

    // Stage poses: 7 floats/cam -> 12-float stride rows.
    const int n_pose_f = n_cam * 7;
    for (int idx = tid; idx < n_pose_f; idx += THREADS) {
        int c = idx / 7;
        int k = idx - c * 7;
        psm[c * POSE_STRIDE + k] = __ldg(&poses[idx]);
    }
    __syncthreads();

    const float fx = __ldg(&K[0]);
    const float cxx = __ldg(&K[2]);
    const float fy = __ldg(&K[4]);
    const float cyy = __ldg(&K[5]);

    const float4* psm4 = (const float4*)psm;

    const int n_quads = n_obs >> 2;
    const int gsz = gridDim.x * THREADS;

    for (int q = blockIdx.x * THREADS + tid; q < n_quads; q += gsz) {
        int4 c4 = __ldg(&cidx4[q]);
        int4 p4 = __ldg(&pidx4[q]);

        float4 ob0 = __ldg(&obs4[2 * q]);
        float4 ob1 = __ldg(&obs4[2 * q + 1]);

        int pis[4] = {p4.x, p4.y, p4.z, p4.w};
        int cis[4] = {c4.x, c4.y, c4.z, c4.w};

        // One LDG.128 per point (issue all 4 up front for MLP)
        float4 pt[4];
        #pragma unroll
        for (int j = 0; j < 4; j++)
            pt[j] = __ldg(&g_points4[pis[j]]);

        // Two LDS.128 per pose
        float4 pa[4], pb[4];
        #pragma unroll
        for (int j = 0; j < 4; j++) {
            pa[j] = psm4[cis[j] * 3];       // tx ty tz qx
            pb[j] = psm4[cis[j] * 3 + 1];   // qy qz qw pad
        }

        float res[8];
        float obx[4] = {ob0.x, ob0.z, ob1.x, ob1.z};
        float oby[4] = {ob0.y, ob0.w, ob1.y, ob1.w};

        #pragma unroll
        for (int j = 0; j < 4; j++) {
            float tx = pa[j].x, ty = pa[j].y, tz = pa[j].z;
            float qx = pa[j].w, qy = pb[j].x, qz = pb[j].y, qw = pb[j].z;
            float X = pt[j].x, Y = pt[j].y, Z = pt[j].z;

            float uvx = qy * Z - qz * Y;
            float uvy = qz * X - qx * Z;
            float uvz = qx * Y - qy * X;
            float wx = fmaf(qw, X, uvx);
            float wy = fmaf(qw, Y, uvy);
            float wz = fmaf(qw, Z, uvz);
            float c2x = qy * wz - qz * wy;
            float c2y = qz * wx - qx * wz;
            float c2z = qx * wy - qy * wx;
            float Xc = fmaf(2.0f, c2x, X) + tx;
            float Yc = fmaf(2.0f, c2y, Y) + ty;
            float Zc = fmaf(2.0f, c2z, Z) + tz;

            float invz = __fdividef(1.0f, Zc);
            res[2 * j + 0] = fmaf(fx * Xc, invz, cxx) - obx[j];
            res[2 * j + 1] = fmaf(fy * Yc, invz, cyy) - oby[j];
        }

        out4[2 * q]     = make_float4(res[0], res[1], res[2], res[3]);
        out4[2 * q + 1] = make_float4(res[4], res[5], res[6], res[7]);
    }

    // ---- tail: n_obs % 4 leftovers (block 0 only) ----
    const int rem_base = n_quads << 2;
    if (blockIdx.x == 0) {
        for (int i = rem_base + tid; i < n_obs; i += THREADS) {
            int ci = __ldg(&cidx[i]);
            int pi = __ldg(&pidx[i]);
            const float* row = psm + ci * POSE_STRIDE;
            float tx = row[0], ty = row[1], tz = row[2];
            float qx = row[3], qy = row[4], qz = row[5], qw = row[6];
            float4 p = __ldg(&g_points4[pi]);
            float X = p.x, Y = p.y, Z = p.z;

            float uvx = qy * Z - qz * Y;
            float uvy = qz * X - qx * Z;
            float uvz = qx * Y - qy * X;
            float wx = fmaf(qw, X, uvx);
            float wy = fmaf(qw, Y, uvy);
            float wz = fmaf(qw, Z, uvz);
            float c2x = qy * wz - qz * wy;
            float c2y = qz * wx - qx * wz;
            float c2z = qx * wy - qy * wx;
            float Xc = fmaf(2.0f, c2x, X) + tx;
            float Yc = fmaf(2.0f, c2y, Y) + ty;
            float Zc = fmaf(2.0f, c2z, Z) + tz;
            float invz = __fdividef(1.0f, Zc);
            float2 ob = __ldg(&obs2[i]);
            float2 r;
            r.x = fmaf(fx * Xc, invz, cxx) - ob.x;
            r.y = fmaf(fy * Yc, invz, cyy) - ob.y;
            out2[i] = r;
        }
    }
}

extern "C" void kernel_launch(void* const* d_in, const int* in_sizes, int n_in,
                              void* d_out, int out_size) {
    const float* observes = (const float*)d_in[0];
    const float* K        = (const float*)d_in[1];
    const float* poses    = (const float*)d_in[2];
    const float* points   = (const float*)d_in[3];
    const int* cidx       = (const int*)d_in[4];
    const int* pidx       = (const int*)d_in[5];

    int n_obs = in_sizes[0] / 2;
    int n_cam = in_sizes[2] / 7;
    int n_pts = in_sizes[3] / 3;
    if (n_pts > N_PTS_MAX) n_pts = N_PTS_MAX;

    int smem = n_cam * POSE_STRIDE * sizeof(float);  // 96000 B for n_cam=2000

    cudaFuncSetAttribute(residual_kernel,
                         cudaFuncAttributeMaxDynamicSharedMemorySize, smem);

    repack_points_kernel<<<(n_pts + 255) / 256, 256>>>(points, n_pts);

    int blocks = 148 * 2;  // 2 blocks/SM (96KB smem each)
    residual_kernel<<<blocks, THREADS, smem>>>(
        (const float4*)observes, K, poses,
        (const int4*)cidx, (const int4*)pidx,
        cidx, pidx, (const float2*)observes,
        (float4*)d_out, (float2*)d_out,
        n_obs, n_cam);
}